// round 1
// baseline (speedup 1.0000x reference)
#include <cuda_runtime.h>
#include <cuda_fp16.h>
#include <cstdint>

// Problem constants (fixed by reference setup_inputs)
constexpr int B = 16384;
constexpr int F = 24;
constexpr int D = 64;
constexpr int P = F * (F - 1) / 2;   // 276
constexpr int MT = 128;              // b-rows per CTA

// Scratch (device globals: allocation-guard safe)
__device__ __half g_xh[(size_t)B * F * D];   // x in fp16, [B][F][D]
__device__ __half g_wt[(size_t)P * D * D];   // W transposed: [p][e][d]

// ---------------- prepass kernels ----------------

__global__ void convert_x_kernel(const float* __restrict__ x) {
    size_t i = ((size_t)blockIdx.x * blockDim.x + threadIdx.x) * 4;
    float4 v = *reinterpret_cast<const float4*>(x + i);
    __half2 h0 = __floats2half2_rn(v.x, v.y);
    __half2 h1 = __floats2half2_rn(v.z, v.w);
    union { uint2 u; __half2 h[2]; } pk;
    pk.h[0] = h0; pk.h[1] = h1;
    *reinterpret_cast<uint2*>(g_xh + i) = pk.u;
}

__global__ void convert_w_kernel(const float* __restrict__ W) {
    int i = blockIdx.x * blockDim.x + threadIdx.x;   // < P*D*D
    int p = i >> 12;          // /4096
    int rem = i & 4095;
    int d = rem >> 6;
    int e = rem & 63;
    g_wt[(size_t)p * D * D + e * D + d] = __float2half_rn(W[i]);
}

__global__ void zero_out_kernel(float* __restrict__ out) {
    out[blockIdx.x * blockDim.x + threadIdx.x] = 0.0f;
}

// ---------------- main kernel ----------------

__device__ __forceinline__ unsigned smem_u32(const void* p) {
    return (unsigned)__cvta_generic_to_shared(p);
}

__device__ __forceinline__ void ldm_x4(unsigned addr, unsigned& r0, unsigned& r1,
                                       unsigned& r2, unsigned& r3) {
    asm volatile("ldmatrix.sync.aligned.m8n8.x4.shared.b16 {%0,%1,%2,%3}, [%4];"
                 : "=r"(r0), "=r"(r1), "=r"(r2), "=r"(r3)
                 : "r"(addr));
}

__device__ __forceinline__ void mma16816(float* c, const unsigned* a,
                                         unsigned b0, unsigned b1) {
    asm volatile(
        "mma.sync.aligned.m16n8k16.row.col.f32.f16.f16.f32 "
        "{%0,%1,%2,%3}, {%4,%5,%6,%7}, {%8,%9}, {%0,%1,%2,%3};"
        : "+f"(c[0]), "+f"(c[1]), "+f"(c[2]), "+f"(c[3])
        : "r"(a[0]), "r"(a[1]), "r"(a[2]), "r"(a[3]), "r"(b0), "r"(b1));
}

// CTA: one pair p × 128 b-rows. 4 warps, each owns 32 rows (2 m16 tiles).
// Y = Xi(128x64,f16) @ Wt^T (i.e. W, 64x64), then logit-partial = rowdot(Y, Xj).
__global__ __launch_bounds__(128) void fmfm_kernel(float* __restrict__ out) {
    const int p  = blockIdx.x;
    const int b0 = blockIdx.y * MT;

    // decode pair p -> (fi, fj), triu row-major order
    int fi = 0, rem = p;
    while (rem >= F - 1 - fi) { rem -= F - 1 - fi; fi++; }
    const int fj = fi + 1 + rem;

    __shared__ alignas(16) __half s_w [D * D];    //  8 KB, swizzled [e][d]
    __shared__ alignas(16) __half s_xi[MT * D];   // 16 KB, swizzled
    __shared__ alignas(16) __half s_xj[MT * D];   // 16 KB, swizzled

    const int t = threadIdx.x;

    // Load W_p^T (64 rows x 8 chunks of 16B), SW128 swizzle: chunk ^= (row&7)
    {
        const uint4* src = reinterpret_cast<const uint4*>(g_wt + (size_t)p * D * D);
        #pragma unroll
        for (int c = t; c < 512; c += 128) {
            int row = c >> 3, ch = c & 7;
            *reinterpret_cast<uint4*>(reinterpret_cast<char*>(s_w) +
                row * 128 + ((ch ^ (row & 7)) << 4)) = src[c];
        }
    }
    // Load Xi, Xj tiles (128 rows x 8 chunks each)
    #pragma unroll
    for (int c = t; c < 1024; c += 128) {
        int row = c >> 3, ch = c & 7;
        const uint4* si = reinterpret_cast<const uint4*>(
            g_xh + ((size_t)(b0 + row) * F + fi) * D);
        const uint4* sj = reinterpret_cast<const uint4*>(
            g_xh + ((size_t)(b0 + row) * F + fj) * D);
        int off = row * 128 + ((ch ^ (row & 7)) << 4);
        *reinterpret_cast<uint4*>(reinterpret_cast<char*>(s_xi) + off) = si[ch];
        *reinterpret_cast<uint4*>(reinterpret_cast<char*>(s_xj) + off) = sj[ch];
    }
    __syncthreads();

    const int warp = t >> 5, lane = t & 31;
    const int group = lane >> 2, tid4 = lane & 3;
    const unsigned xi_base = smem_u32(s_xi);
    const unsigned w_base  = smem_u32(s_w);

    float acc[2][8][4];
    #pragma unroll
    for (int a = 0; a < 2; a++)
        #pragma unroll
        for (int b = 0; b < 8; b++)
            #pragma unroll
            for (int c = 0; c < 4; c++) acc[a][b][c] = 0.0f;

    #pragma unroll
    for (int ks = 0; ks < 4; ks++) {
        // A fragments for this warp's 2 m-tiles
        unsigned a[2][4];
        #pragma unroll
        for (int mt = 0; mt < 2; mt++) {
            int r  = warp * 32 + mt * 16 + (lane & 15);
            int ch = ks * 2 + (lane >> 4);
            ldm_x4(xi_base + r * 128 + ((ch ^ (r & 7)) << 4),
                   a[mt][0], a[mt][1], a[mt][2], a[mt][3]);
        }
        // B fragments: 2 n-tiles per ldmatrix.x4
        #pragma unroll
        for (int nt2 = 0; nt2 < 4; nt2++) {
            unsigned br0, br1, br2, br3;
            int r  = nt2 * 16 + (lane & 15);
            int ch = ks * 2 + (lane >> 4);
            ldm_x4(w_base + r * 128 + ((ch ^ (r & 7)) << 4), br0, br1, br2, br3);
            #pragma unroll
            for (int mt = 0; mt < 2; mt++) {
                mma16816(acc[mt][nt2 * 2],     a[mt], br0, br2);
                mma16816(acc[mt][nt2 * 2 + 1], a[mt], br1, br3);
            }
        }
    }

    // Epilogue: sum_e Y[r,e] * Xj[r,e]
    // acc[mt][nt][0/1] -> row (base+group),   cols nt*8 + tid4*2 + {0,1}
    // acc[mt][nt][2/3] -> row (base+group+8), same cols
    #pragma unroll
    for (int mt = 0; mt < 2; mt++) {
        const int r0 = warp * 32 + mt * 16 + group;
        const int r1 = r0 + 8;
        float s0 = 0.0f, s1 = 0.0f;
        #pragma unroll
        for (int nt = 0; nt < 8; nt++) {
            const __half2 x0 = *reinterpret_cast<const __half2*>(
                reinterpret_cast<const char*>(s_xj) +
                r0 * 128 + ((nt ^ (r0 & 7)) << 4) + tid4 * 4);
            const __half2 x1 = *reinterpret_cast<const __half2*>(
                reinterpret_cast<const char*>(s_xj) +
                r1 * 128 + ((nt ^ (r1 & 7)) << 4) + tid4 * 4);
            float2 f0 = __half22float2(x0);
            float2 f1 = __half22float2(x1);
            s0 = fmaf(acc[mt][nt][0], f0.x, s0);
            s0 = fmaf(acc[mt][nt][1], f0.y, s0);
            s1 = fmaf(acc[mt][nt][2], f1.x, s1);
            s1 = fmaf(acc[mt][nt][3], f1.y, s1);
        }
        // reduce over the 4 lanes of the quad (tid4)
        s0 += __shfl_xor_sync(0xffffffffu, s0, 1);
        s0 += __shfl_xor_sync(0xffffffffu, s0, 2);
        s1 += __shfl_xor_sync(0xffffffffu, s1, 1);
        s1 += __shfl_xor_sync(0xffffffffu, s1, 2);
        if (tid4 == 0) {
            atomicAdd(out + b0 + r0, s0);
            atomicAdd(out + b0 + r1, s1);
        }
    }
}

// ---------------- launch ----------------

extern "C" void kernel_launch(void* const* d_in, const int* in_sizes, int n_in,
                              void* d_out, int out_size) {
    const float* x = (const float*)d_in[0];
    const float* W = (const float*)d_in[1];
    float* out = (float*)d_out;

    convert_x_kernel<<<(B * F * D) / 1024, 256>>>(x);   // 4 elems/thread
    convert_w_kernel<<<(P * D * D) / 256, 256>>>(W);
    zero_out_kernel<<<B / 256, 256>>>(out);

    dim3 grid(P, B / MT);   // x = pair (fast), y = b-tile -> L2 locality per b-tile
    fmfm_kernel<<<grid, 128>>>(out);
}

// round 3
// speedup vs baseline: 1.3187x; 1.3187x over previous
#include <cuda_runtime.h>
#include <cuda_fp16.h>
#include <cstdint>

// ---------------- problem constants ----------------
constexpr int B  = 16384;
constexpr int F  = 24;
constexpr int P  = 276;
constexpr int MT = 128;                  // b-rows per CTA
constexpr int NTILE = B / MT;            // 128 b-tiles
constexpr int XTILE = MT * 128;          // 16 KB per (tile, field), fp16, swizzled
constexpr int WTILE = 64 * 128;          // 8 KB per pair (W^T fp16, swizzled)
constexpr unsigned WOFF = 12 * XTILE;            // 196608
constexpr unsigned DYN_SMEM = WOFF + 2 * WTILE;  // 212992 (208 KB)

// ---------------- device scratch (allocation-guard safe) ----------------
__device__ __half g_xs[(size_t)NTILE * F * (XTILE / 2)];  // 48 MB preswizzled x tiles
__device__ __half g_ws[(size_t)P * (WTILE / 2)];          // 2.25 MB preswizzled W^T tiles

// ---------------- helpers ----------------
__device__ __forceinline__ unsigned smem_u32(const void* p) {
    return (unsigned)__cvta_generic_to_shared(p);
}
__device__ __forceinline__ void cp16(unsigned dst, const void* src) {
    asm volatile("cp.async.cg.shared.global [%0], [%1], 16;" :: "r"(dst), "l"(src));
}
__device__ __forceinline__ void cp_commit() {
    asm volatile("cp.async.commit_group;" ::: "memory");
}
__device__ __forceinline__ void cp_wait0() {
    asm volatile("cp.async.wait_group 0;" ::: "memory");
}
__device__ __forceinline__ void cp_wait1() {
    asm volatile("cp.async.wait_group 1;" ::: "memory");
}
__device__ __forceinline__ void ldm_x4(unsigned addr, unsigned& r0, unsigned& r1,
                                       unsigned& r2, unsigned& r3) {
    asm volatile("ldmatrix.sync.aligned.m8n8.x4.shared.b16 {%0,%1,%2,%3}, [%4];"
                 : "=r"(r0), "=r"(r1), "=r"(r2), "=r"(r3)
                 : "r"(addr));
}
__device__ __forceinline__ void mma16816(float* c, const unsigned* a,
                                         unsigned b0, unsigned b1) {
    asm volatile(
        "mma.sync.aligned.m16n8k16.row.col.f32.f16.f16.f32 "
        "{%0,%1,%2,%3}, {%4,%5,%6,%7}, {%8,%9}, {%0,%1,%2,%3};"
        : "+f"(c[0]), "+f"(c[1]), "+f"(c[2]), "+f"(c[3])
        : "r"(a[0]), "r"(a[1]), "r"(a[2]), "r"(a[3]), "r"(b0), "r"(b1));
}
__device__ __forceinline__ int pidx(int fi, int fj) {   // triu row-major pair index
    return fi * (2 * F - fi - 1) / 2 + (fj - fi - 1);
}

// ---------------- prepass: convert + pre-swizzle ----------------
__global__ void convert_x_kernel(const float* __restrict__ x) {
    int t = blockIdx.x * blockDim.x + threadIdx.x;      // chunk id < B*F*8
    int c = t & 7;
    int bf = t >> 3;
    int f = bf % F;
    int b = bf / F;
    const float4* src = reinterpret_cast<const float4*>(x + ((size_t)bf * 64 + c * 8));
    float4 v0 = src[0], v1 = src[1];
    union { uint4 u; __half2 h[4]; } pk;
    pk.h[0] = __floats2half2_rn(v0.x, v0.y);
    pk.h[1] = __floats2half2_rn(v0.z, v0.w);
    pk.h[2] = __floats2half2_rn(v1.x, v1.y);
    pk.h[3] = __floats2half2_rn(v1.z, v1.w);
    int tile = b >> 7, r = b & 127;
    size_t off = ((size_t)(tile * 24 + f) << 14) + r * 128 + ((c ^ (r & 7)) << 4);
    *reinterpret_cast<uint4*>(reinterpret_cast<char*>(g_xs) + off) = pk.u;
}
// W[p,d,e] fp32 -> preswizzled W^T tile: row e, chunk c holds d = c*8..c*8+7
__global__ void convert_w_kernel(const float* __restrict__ W) {
    int t = blockIdx.x * blockDim.x + threadIdx.x;      // < P*8*64
    int e = t & 63;
    int pc = t >> 6;
    int c = pc & 7;
    int p = pc >> 3;
    const float* base = W + (size_t)p * 4096 + (size_t)c * 8 * 64 + e;
    union { uint4 u; __half h[8]; } pk;
    #pragma unroll
    for (int k = 0; k < 8; k++) pk.h[k] = __float2half_rn(base[k * 64]);
    size_t off = (size_t)p * 8192 + e * 128 + ((c ^ (e & 7)) << 4);
    *reinterpret_cast<uint4*>(reinterpret_cast<char*>(g_ws) + off) = pk.u;
}
__global__ void zero_out_kernel(float* __restrict__ out) {
    out[blockIdx.x * blockDim.x + threadIdx.x] = 0.0f;
}

// ---------------- main kernel ----------------
// grid = (128 b-tiles, 6 types). 12 x field tiles resident in smem.
// Per j: accumulate GEMM over i-partners in registers, one epilogue dot per j.
__global__ __launch_bounds__(128, 1) void fmfm3_kernel(float* __restrict__ out) {
    extern __shared__ __align__(1024) char smem[];
    const int tid  = threadIdx.x;
    const int warp = tid >> 5, lane = tid & 31;
    const int group = lane >> 2, tid4 = lane & 3;
    const int tile = blockIdx.x;
    const int type = blockIdx.y;
    const int b0   = tile * MT;

    const bool cross = (type >= 2);
    int fb0, fb1, nJ, npairs;
    if (!cross) { fb0 = type * 12; fb1 = 0; nJ = 11; npairs = 66; }
    else {
        int t = type - 2;
        fb0 = (t >> 1) * 6;          // i-side fields -> slots 0..5
        fb1 = 12 + (t & 1) * 6;      // j-side fields -> slots 6..11
        nJ = 6; npairs = 36;
    }

    const unsigned sb = smem_u32(smem);

    // ---- load 12 x field tiles (preswizzled, linear copy) ----
    #pragma unroll
    for (int s = 0; s < 12; s++) {
        int f = cross ? (s < 6 ? fb0 + s : fb1 + (s - 6)) : (fb0 + s);
        const char* g = reinterpret_cast<const char*>(g_xs) + ((size_t)(tile * 24 + f) << 14);
        #pragma unroll
        for (int c = tid; c < 1024; c += 128)
            cp16(sb + s * XTILE + c * 16, g + c * 16);
    }
    cp_commit();
    // ---- prefetch W for pair 0 ----
    {
        int p0 = cross ? pidx(fb0, fb1) : pidx(fb0, fb0 + 1);
        const char* g = reinterpret_cast<const char*>(g_ws) + (size_t)p0 * WTILE;
        #pragma unroll
        for (int c = tid; c < 512; c += 128)
            cp16(sb + WOFF + c * 16, g + c * 16);
        cp_commit();
    }
    cp_wait0();
    __syncthreads();

    float tot[2][2] = {{0.f, 0.f}, {0.f, 0.f}};
    int n = 0;   // pair sequence counter

    for (int jidx = 0; jidx < nJ; jidx++) {
        const int na = cross ? 6 : jidx + 1;     // number of i-partners
        const int jslot = cross ? 6 + jidx : jidx + 1;

        float acc[2][8][4];
        #pragma unroll
        for (int a = 0; a < 2; a++)
            #pragma unroll
            for (int b = 0; b < 8; b++)
                #pragma unroll
                for (int c = 0; c < 4; c++) acc[a][b][c] = 0.0f;

        for (int aa = 0; aa < na; aa++, n++) {
            // prefetch W for pair (n+1) mod npairs into the other buffer
            {
                int m = n + 1; if (m == npairs) m = 0;
                // decode m -> (j2, i2)
                int j2, i2;
                if (cross) { j2 = m / 6; i2 = m % 6; }
                else {
                    j2 = 0; int rem = m;
                    while (rem > j2) { rem -= j2 + 1; j2++; }   // sum_{k<=j2} k pattern
                    i2 = rem;
                }
                int pfi = fb0 + i2;
                int pfj = cross ? fb1 + j2 : fb0 + j2 + 1;
                int p = pidx(pfi, pfj);
                const char* g = reinterpret_cast<const char*>(g_ws) + (size_t)p * WTILE;
                unsigned dstb = sb + WOFF + ((unsigned)(m & 1)) * WTILE;
                #pragma unroll
                for (int c = tid; c < 512; c += 128)
                    cp16(dstb + c * 16, g + c * 16);
                cp_commit();
            }
            cp_wait1();
            __syncthreads();        // W buf (n&1) ready

            const unsigned xi_base = sb + (unsigned)aa * XTILE;
            const unsigned w_base  = sb + WOFF + ((unsigned)(n & 1)) * WTILE;

            #pragma unroll
            for (int ks = 0; ks < 4; ks++) {
                unsigned a[2][4];
                #pragma unroll
                for (int mt = 0; mt < 2; mt++) {
                    int r  = warp * 32 + mt * 16 + (lane & 15);
                    int ch = ks * 2 + (lane >> 4);
                    ldm_x4(xi_base + r * 128 + ((ch ^ (r & 7)) << 4),
                           a[mt][0], a[mt][1], a[mt][2], a[mt][3]);
                }
                #pragma unroll
                for (int nt2 = 0; nt2 < 4; nt2++) {
                    unsigned br0, br1, br2, br3;
                    int r  = nt2 * 16 + (lane & 15);
                    int ch = ks * 2 + (lane >> 4);
                    ldm_x4(w_base + r * 128 + ((ch ^ (r & 7)) << 4), br0, br1, br2, br3);
                    #pragma unroll
                    for (int mt = 0; mt < 2; mt++) {
                        mma16816(acc[mt][nt2 * 2],     a[mt], br0, br2);
                        mma16816(acc[mt][nt2 * 2 + 1], a[mt], br1, br3);
                    }
                }
            }
            __syncthreads();        // all reads of W buf done before overwrite
        }

        // ---- epilogue for j: dot rows of acc with x_j ----
        #pragma unroll
        for (int mt = 0; mt < 2; mt++) {
            const int r0 = warp * 32 + mt * 16 + group;
            const int r1 = r0 + 8;
            float s0 = 0.0f, s1 = 0.0f;
            const char* xj = smem + jslot * XTILE;
            #pragma unroll
            for (int nt = 0; nt < 8; nt++) {
                const __half2 x0 = *reinterpret_cast<const __half2*>(
                    xj + r0 * 128 + ((nt ^ (r0 & 7)) << 4) + tid4 * 4);
                const __half2 x1 = *reinterpret_cast<const __half2*>(
                    xj + r1 * 128 + ((nt ^ (r1 & 7)) << 4) + tid4 * 4);
                float2 f0 = __half22float2(x0);
                float2 f1 = __half22float2(x1);
                s0 = fmaf(acc[mt][nt][0], f0.x, s0);
                s0 = fmaf(acc[mt][nt][1], f0.y, s0);
                s1 = fmaf(acc[mt][nt][2], f1.x, s1);
                s1 = fmaf(acc[mt][nt][3], f1.y, s1);
            }
            tot[mt][0] += s0;
            tot[mt][1] += s1;
        }
    }

    // ---- final reduction + writeback (one atomicAdd per row) ----
    #pragma unroll
    for (int mt = 0; mt < 2; mt++)
        #pragma unroll
        for (int h = 0; h < 2; h++) {
            float v = tot[mt][h];
            v += __shfl_xor_sync(0xffffffffu, v, 1);
            v += __shfl_xor_sync(0xffffffffu, v, 2);
            if (tid4 == 0)
                atomicAdd(out + b0 + warp * 32 + mt * 16 + group + h * 8, v);
        }
}

// ---------------- launch ----------------
extern "C" void kernel_launch(void* const* d_in, const int* in_sizes, int n_in,
                              void* d_out, int out_size) {
    const float* x = (const float*)d_in[0];
    const float* W = (const float*)d_in[1];
    float* out = (float*)d_out;

    static bool attr_done = false;
    if (!attr_done) {
        cudaFuncSetAttribute(fmfm3_kernel, cudaFuncAttributeMaxDynamicSharedMemorySize, DYN_SMEM);
        attr_done = true;
    }

    convert_x_kernel<<<(B * F * 8) / 256, 256>>>(x);
    convert_w_kernel<<<(P * 8 * 64) / 256, 256>>>(W);
    zero_out_kernel<<<B / 256, 256>>>(out);

    dim3 grid(NTILE, 6);
    fmfm3_kernel<<<grid, 128, DYN_SMEM>>>(out);
}